// round 13
// baseline (speedup 1.0000x reference)
#include <cuda_runtime.h>
#include <cstdint>
#include <cstring>
#include <vector>
#include <thread>
#include <algorithm>

// ---------------------------------------------------------------------------
// quan_Linear_fi — R13: no c materialization. Lane owns 16 CONSECUTIVE
// elements -> cumsum needs only ONE 5-shuffle warp scan per row (was 24
// shuffles), so recomputing the cumsum in M2 (bit-identical fp sequence)
// is cheaper than the 536MB store/load it replaces. Host threefry (R10/12)
// supplies sparse flips. Planes: p 9..15, c 7..15, y 0..15.
// ---------------------------------------------------------------------------

#define FLIP_T  43008u
#define P_KMIN 9
#define P_NP   7
#define C_KMIN 7
#define C_NP   9
#define Y_NP   16

// Arena layout (uint32 units).
#define BM_P   0u          // 4096 words: 131072 row bits (p tensor)
#define BM_C   4096u       // 4096 words (c tensor)
#define ENT_P  8192u       // up to 8192 packed entries (j<<4 | plane)
#define ENT_C  16384u      // up to 8192 packed entries
#define COLW   24576u      // 512 floats: colmax|w|
#define COLX   25088u      // 512 floats: colmax|x|
#define ARENA_W 25600u

__device__ uint32_t g_arena[ARENA_W];
__device__ float    g_wq[512 * 512];
__device__ float    g_Y[131072];       // y before final bitflip, [b,o,s]
__device__ unsigned g_maxw_bits, g_maxp_bits, g_maxc_bits, g_maxy_bits;

// ---------------------- uploader (kernel-arg -> arena) ---------------------
#define CHUNK_W 8000
struct Chunk { uint32_t n, dst; uint32_t data[CHUNK_W]; };   // 32008-byte arg

__global__ void k_upload(Chunk c) {
    unsigned i = blockIdx.x * blockDim.x + threadIdx.x;
    if (i < c.n) g_arena[c.dst + i] = c.data[i];
}

// Scatter row bits from packed entries; zero the max registers.
// Idempotent across graph replays (same flip set every time).
__global__ void k_scatter(int np, int nc) {
    int i = blockIdx.x * blockDim.x + threadIdx.x;
    if (i == 0) {
        g_maxw_bits = 0u; g_maxp_bits = 0u; g_maxc_bits = 0u; g_maxy_bits = 0u;
    }
    if (i < np) {
        unsigned row = g_arena[ENT_P + i] >> 13;     // (j<<4)>>13 = j>>9
        atomicOr(&g_arena[BM_P + (row >> 5)], 1u << (row & 31));
    }
    if (i < nc) {
        unsigned row = g_arena[ENT_C + i] >> 13;
        atomicOr(&g_arena[BM_C + (row >> 5)], 1u << (row & 31));
    }
}

struct YF { int n; uint32_t j[120]; uint32_t msk[120]; };

// 16-bit fixed-point quantize (round-nearest-even) + XOR fault.
__device__ __forceinline__ float qflip(float t, float inv, float scale,
                                       uint32_t mask) {
    float r = rintf(t * inv);
    r = fminf(fmaxf(r, -32768.0f), 32767.0f);
    if (mask) {
        int q = (int)r;
        q = (int)(((uint32_t)(q + 32768) ^ mask)) - 32768;
        r = (float)q;
    }
    return r * scale;
}

// Load this row's sparse flip masks into m[16]; element e = lane*16 + u.
// Entries are packed (j<<4 | plane), sorted ascending (j-major).
__device__ __forceinline__ void load_masks(unsigned* m, int row, int lane,
                                           uint32_t bm_off, uint32_t ent_off,
                                           int n_ent) {
    #pragma unroll
    for (int e = 0; e < 16; ++e) m[e] = 0u;
    unsigned word = g_arena[bm_off + (row >> 5)];
    if ((word >> (row & 31)) & 1u) {
        int lo = 0, hi = n_ent;
        while (lo < hi) {
            int mid = (lo + hi) >> 1;
            if ((int)(g_arena[ent_off + mid] >> 13) < row) lo = mid + 1; else hi = mid;
        }
        while (lo < n_ent) {
            unsigned v = g_arena[ent_off + lo];
            if ((int)(v >> 13) != row) break;
            int e = (v >> 4) & 511;
            unsigned mask = 1u << (v & 15u);
            if ((e >> 4) == lane) {
                int slot = e & 15;
                #pragma unroll
                for (int t2 = 0; t2 < 16; ++t2) if (slot == t2) m[t2] |= mask;
            }
            ++lo;
        }
    }
}

// ---------------------------- front kernels --------------------------------
__global__ void k_colmax(const float* __restrict__ x, const float* __restrict__ w) {
    int i = blockIdx.x;                  // column 0..511
    int t = threadIdx.x;                 // 256 threads
    float cw = fmaxf(fabsf(w[t * 512 + i]), fabsf(w[(t + 256) * 512 + i]));
    float cx = fabsf(x[t * 512 + i]);
    __shared__ float sw[8], sx[8];
    #pragma unroll
    for (int d = 16; d; d >>= 1) {
        cw = fmaxf(cw, __shfl_xor_sync(0xffffffffu, cw, d));
        cx = fmaxf(cx, __shfl_xor_sync(0xffffffffu, cx, d));
    }
    if ((t & 31) == 0) { sw[t >> 5] = cw; sx[t >> 5] = cx; }
    __syncthreads();
    if (t == 0) {
        float mw = sw[0], mx = sx[0];
        #pragma unroll
        for (int u = 1; u < 8; ++u) { mw = fmaxf(mw, sw[u]); mx = fmaxf(mx, sx[u]); }
        ((float*)g_arena)[COLW + i] = mw;
        ((float*)g_arena)[COLX + i] = mx;
        atomicMax(&g_maxw_bits, __float_as_uint(mw));
    }
}

__global__ void k_wq(const float* __restrict__ w) {
    float step = __uint_as_float(g_maxw_bits) / 127.0f;
    int e = blockIdx.x * blockDim.x + threadIdx.x;
    if (e < 262144) {
        float q = rintf(w[e] / step);
        q = fminf(fmaxf(q, -128.0f), 127.0f);
        g_wq[e] = q * step;
    }
}

__global__ void k_scalep() {
    int i = threadIdx.x;                 // 512 threads, 1 block
    float step = __uint_as_float(g_maxw_bits) / 127.0f;
    float cw = ((float*)g_arena)[COLW + i];
    float cx = ((float*)g_arena)[COLX + i];
    float qw = fminf(rintf(cw / step), 127.0f) * step;
    __shared__ float sm[512];
    sm[i] = cx * qw;
    __syncthreads();
    for (int d = 256; d; d >>= 1) {
        if (i < d) sm[i] = fmaxf(sm[i], sm[i + d]);
        __syncthreads();
    }
    if (i == 0) g_maxp_bits = __float_as_uint(sm[0]);
}

// Shared row-cumsum body. Lane owns elements lane*16 + u (u=0..15).
// MUST be bit-identical between M1 and M2 (same fp sequence).
// Returns the 16 inclusive-cumsum values in cvals[].
__device__ __forceinline__ void row_cumsum(const float4* X4, const float4* W4,
                                           float ip, float sp,
                                           const unsigned* m, int lane,
                                           float* cvals) {
    float f[16];
    #pragma unroll
    for (int q = 0; q < 4; ++q) {
        float4 xv = X4[lane * 4 + q];
        float4 wv = W4[lane * 4 + q];
        f[q * 4 + 0] = qflip(xv.x * wv.x, ip, sp, m[q * 4 + 0]);
        f[q * 4 + 1] = qflip(xv.y * wv.y, ip, sp, m[q * 4 + 1]);
        f[q * 4 + 2] = qflip(xv.z * wv.z, ip, sp, m[q * 4 + 2]);
        f[q * 4 + 3] = qflip(xv.w * wv.w, ip, sp, m[q * 4 + 3]);
    }
    float run = 0.0f;
    #pragma unroll
    for (int u = 0; u < 16; ++u) { run += f[u]; cvals[u] = run; }
    float T = run;                         // inclusive scan of lane totals
    #pragma unroll
    for (int d = 1; d < 32; d <<= 1) {
        float v = __shfl_up_sync(0xffffffffu, T, d);
        if (lane >= d) T += v;
    }
    float base = T - run;                  // exclusive prefix for this lane
    #pragma unroll
    for (int u = 0; u < 16; ++u) cvals[u] += base;
}

// ---------------- M1: faulty-p cumsum, track max|c| (no store) -------------
__global__ void __launch_bounds__(256)
k_m1(const float* __restrict__ x, int n_ent) {
    int wid  = (blockIdx.x * 256 + threadIdx.x) >> 5;   // 0..131071
    int lane = threadIdx.x & 31;
    int b  = wid >> 16;
    int os = wid & 65535;
    int o = os >> 7, s = os & 127;

    unsigned m[16];
    load_masks(m, wid, lane, BM_P, ENT_P, n_ent);

    float mp = __uint_as_float(g_maxp_bits);
    float sp = mp / 32767.0f; if (!(sp > 0.0f)) sp = 1.0f;
    float ip = 1.0f / sp;
    const float4* X4 = (const float4*)(x + b * 65536 + s * 512);
    const float4* W4 = (const float4*)(g_wq + o * 512);

    float c[16];
    row_cumsum(X4, W4, ip, sp, m, lane, c);

    float mx = 0.0f;
    #pragma unroll
    for (int u = 0; u < 16; ++u) mx = fmaxf(mx, fabsf(c[u]));
    #pragma unroll
    for (int d = 16; d; d >>= 1) mx = fmaxf(mx, __shfl_xor_sync(0xffffffffu, mx, d));

    __shared__ unsigned smax;
    if (threadIdx.x == 0) smax = 0u;
    __syncthreads();
    if (lane == 0) atomicMax(&smax, __float_as_uint(mx));
    __syncthreads();
    if (threadIdx.x == 0) atomicMax(&g_maxc_bits, smax);
}

// ------- M2: recompute cumsum (bit-identical), quantize c, y_sum/c_error ---
__global__ void __launch_bounds__(256)
k_m2(const float* __restrict__ x, int np_ent, int nc_ent) {
    int wid  = (blockIdx.x * 256 + threadIdx.x) >> 5;   // 0..131071
    int lane = threadIdx.x & 31;
    int b  = wid >> 16;
    int os = wid & 65535;
    int o = os >> 7, s = os & 127;

    unsigned mp_[16], mc_[16];
    load_masks(mp_, wid, lane, BM_P, ENT_P, np_ent);
    load_masks(mc_, wid, lane, BM_C, ENT_C, nc_ent);

    float mp = __uint_as_float(g_maxp_bits);
    float sp = mp / 32767.0f; if (!(sp > 0.0f)) sp = 1.0f;
    float ip = 1.0f / sp;
    float mc = __uint_as_float(g_maxc_bits);
    float sc2 = mc / 32767.0f; if (!(sc2 > 0.0f)) sc2 = 1.0f;
    float ic = 1.0f / sc2;
    const float4* X4 = (const float4*)(x + b * 65536 + s * 512);
    const float4* W4 = (const float4*)(g_wq + o * 512);

    float c[16];
    row_cumsum(X4, W4, ip, sp, mp_, lane, c);

    float e = 0.0f, d_first = 0.0f, d_last = 0.0f, y_last = 0.0f;
    #pragma unroll
    for (int u = 0; u < 16; ++u) {
        float g = qflip(c[u], ic, sc2, mc_[u]);
        float d = g - c[u];
        e += d;
        if (lane == 0  && u == 0)  d_first = d;               // i = 0
        if (lane == 31 && u == 15) { d_last = d; y_last = g; } // i = 511
    }
    #pragma unroll
    for (int d = 16; d; d >>= 1) e += __shfl_xor_sync(0xffffffffu, e, d);
    d_first = __shfl_sync(0xffffffffu, d_first, 0);
    d_last  = __shfl_sync(0xffffffffu, d_last, 31);
    y_last  = __shfl_sync(0xffffffffu, y_last, 31);

    __shared__ unsigned smax;
    if (threadIdx.x == 0) smax = 0u;
    __syncthreads();
    if (lane == 0) {
        float y = y_last + (e - d_first - d_last);
        g_Y[wid] = y;                                   // [b,o,s] flat == wid
        atomicMax(&smax, __float_as_uint(fabsf(y)));
    }
    __syncthreads();
    if (threadIdx.x == 0) atomicMax(&g_maxy_bits, smax);
}

// ---------------- M3: final y bitflip + transpose + bias -------------------
__global__ void k_m3(const float* __restrict__ bias, float* __restrict__ out,
                     YF yf) {
    int t = blockIdx.x * blockDim.x + threadIdx.x;   // 0..65535
    int o = t & 511, s = t >> 9;
    float my = __uint_as_float(g_maxy_bits);
    float sy = my / 32767.0f; if (!(sy > 0.0f)) sy = 1.0f;
    float iy = 1.0f / sy;
    unsigned j0 = (unsigned)(o * 128 + s);
    unsigned j1 = j0 + 65536u;
    unsigned m0 = 0u, m1 = 0u;
    for (int i = 0; i < yf.n; ++i) {
        if (yf.j[i] == j0) m0 |= yf.msk[i];
        if (yf.j[i] == j1) m1 |= yf.msk[i];
    }
    float y0 = g_Y[j0];
    float y1 = g_Y[j1];
    float b  = bias[o];
    out[(0 * 128 + s) * 512 + o] = qflip(y0, iy, sy, m0) + b;
    out[(1 * 128 + s) * 512 + o] = qflip(y1, iy, sy, m1) + b;
}

// ---------------------------- host side ------------------------------------
struct HSched { uint32_t A0, B0, A1, B1, A2, B2, A3, B3, A4, B4, A5, B5; };

static void h_threefry(uint32_t k0, uint32_t k1, uint32_t x0, uint32_t x1,
                       uint32_t& o0, uint32_t& o1) {
    uint32_t k2 = k0 ^ k1 ^ 0x1BD11BDAu;
    auto rot = [](uint32_t v, int r) { return (v << r) | (v >> (32 - r)); };
    auto rnd = [&](int r) { x0 += x1; x1 = rot(x1, r); x1 ^= x0; };
    x0 += k0; x1 += k1;
    rnd(13); rnd(15); rnd(26); rnd(6);   x0 += k1; x1 += k2 + 1u;
    rnd(17); rnd(29); rnd(16); rnd(24);  x0 += k2; x1 += k0 + 2u;
    rnd(13); rnd(15); rnd(26); rnd(6);   x0 += k0; x1 += k1 + 3u;
    rnd(17); rnd(29); rnd(16); rnd(24);  x0 += k1; x1 += k2 + 4u;
    rnd(13); rnd(15); rnd(26); rnd(6);   x0 += k2; x1 += k0 + 5u;
    o0 = x0; o1 = x1;
}

static void h_foldin(uint32_t k0, uint32_t k1, uint32_t d,
                     uint32_t& o0, uint32_t& o1) {
    h_threefry(k0, k1, 0u, d, o0, o1);
}

static HSched h_sched(uint32_t k0, uint32_t k1) {
    uint32_t k2 = k0 ^ k1 ^ 0x1BD11BDAu;
    HSched s;
    s.A0 = k0; s.B0 = k1;
    s.A1 = k1; s.B1 = k2 + 1u;
    s.A2 = k2; s.B2 = k0 + 2u;
    s.A3 = k0; s.B3 = k1 + 3u;
    s.A4 = k1; s.B4 = k2 + 4u;
    s.A5 = k2; s.B5 = k0 + 5u;
    return s;
}

static inline uint32_t tf_host(const HSched& s, uint32_t j) {
    uint32_t x0 = s.A0, x1 = j + s.B0;
    auto R = [&](int r) { x0 += x1; x1 = (x1 << r) | (x1 >> (32 - r)); x1 ^= x0; };
    R(13); R(15); R(26); R(6);   x0 += s.A1; x1 += s.B1;
    R(17); R(29); R(16); R(24);  x0 += s.A2; x1 += s.B2;
    R(13); R(15); R(26); R(6);   x0 += s.A3; x1 += s.B3;
    R(17); R(29); R(16); R(24);  x0 += s.A4; x1 += s.B4;
    R(13); R(15); R(26); R(6);   x0 += s.A5; x1 += s.B5;
    return x0 ^ x1;
}

// Collect packed flips (j<<4 | plane), sorted ascending (j-major).
static void collect_packed(const HSched* scheds, const int* planes, int nk,
                           uint32_t N, std::vector<uint32_t>& out) {
    unsigned T = std::thread::hardware_concurrency();
    if (T == 0) T = 8;
    if (T > 48) T = 48;
    uint32_t chunk = ((N / T + 511u) / 512u) * 512u;
    if (chunk == 0) chunk = N;
    std::vector<std::vector<uint32_t>> res(T);
    auto work = [&](unsigned t) {
        uint64_t lo = (uint64_t)t * chunk;
        if (lo >= N) return;
        uint64_t hi = lo + chunk; if (hi > N) hi = N;
        auto& v = res[t];
        for (int k = 0; k < nk; ++k) {
            HSched s = scheds[k];
            uint32_t pl = (uint32_t)planes[k];
            for (uint64_t j = lo; j < hi; ++j)
                if (tf_host(s, (uint32_t)j) < FLIP_T)
                    v.push_back(((uint32_t)j << 4) | pl);
        }
        std::sort(v.begin(), v.end());
    };
    std::vector<std::thread> th;
    unsigned started = 0;
    try {
        for (; started < T; ++started) th.emplace_back(work, started);
    } catch (...) {}
    for (auto& x : th) x.join();
    for (unsigned t = started; t < T; ++t) work(t);   // serial fallback
    for (unsigned t = 0; t < T; ++t)
        out.insert(out.end(), res[t].begin(), res[t].end());
}

extern "C" void kernel_launch(void* const* d_in, const int* in_sizes, int n_in,
                              void* d_out, int out_size) {
    const float* x    = (const float*)d_in[0];
    const float* w    = (const float*)d_in[1];
    const float* bias = (const float*)d_in[2];
    float* out        = (float*)d_out;

    // fikey = jax.random.key(42) -> (0,42); per-tensor, per-plane keys.
    uint32_t p0, p1, c0, c1, y0, y1, a, b;
    h_foldin(0u, 42u, 0u, p0, p1);
    h_foldin(0u, 42u, 1u, c0, c1);
    h_foldin(0u, 42u, 2u, y0, y1);

    HSched sp[P_NP]; int bp[P_NP];
    for (int k = 0; k < P_NP; ++k) {
        h_foldin(p0, p1, (uint32_t)(P_KMIN + k), a, b);
        sp[k] = h_sched(a, b); bp[k] = P_KMIN + k;
    }
    HSched sc[C_NP]; int bc[C_NP];
    for (int k = 0; k < C_NP; ++k) {
        h_foldin(c0, c1, (uint32_t)(C_KMIN + k), a, b);
        sc[k] = h_sched(a, b); bc[k] = C_KMIN + k;
    }
    HSched sy[Y_NP]; int by[Y_NP];
    for (int k = 0; k < Y_NP; ++k) {
        h_foldin(y0, y1, (uint32_t)k, a, b);
        sy[k] = h_sched(a, b); by[k] = k;
    }

    // Host RNG: all flip positions (input-independent, deterministic).
    std::vector<uint32_t> fp, fc, fy;
    collect_packed(sp, bp, P_NP, 67108864u, fp);
    collect_packed(sc, bc, C_NP, 67108864u, fc);
    collect_packed(sy, by, Y_NP, 131072u, fy);

    int np = (int)std::min<size_t>(fp.size(), 8000);
    int nc = (int)std::min<size_t>(fc.size(), 8000);

    YF yf; yf.n = 0;
    for (uint32_t v : fy) {
        uint32_t j = v >> 4, msk = 1u << (v & 15u);
        if (yf.n && yf.j[yf.n - 1] == j) yf.msk[yf.n - 1] |= msk;
        else if (yf.n < 120) { yf.j[yf.n] = j; yf.msk[yf.n] = msk; ++yf.n; }
    }

    // Upload packed entries (one chunk each), then scatter bitmaps + zero regs.
    Chunk ch;
    if (np) {
        ch.n = (uint32_t)np; ch.dst = ENT_P;
        memcpy(ch.data, fp.data(), np * 4);
        k_upload<<<(np + 255) / 256, 256>>>(ch);
    }
    if (nc) {
        ch.n = (uint32_t)nc; ch.dst = ENT_C;
        memcpy(ch.data, fc.data(), nc * 4);
        k_upload<<<(nc + 255) / 256, 256>>>(ch);
    }
    int nmax = np > nc ? np : nc; if (nmax < 1) nmax = 1;
    k_scatter<<<(nmax + 255) / 256, 256>>>(np, nc);

    k_colmax<<<512, 256>>>(x, w);
    k_wq    <<<1024, 256>>>(w);
    k_scalep<<<1, 512>>>();
    k_m1    <<<16384, 256>>>(x, np);        // 131072 warps: one per (b,o,s)
    k_m2    <<<16384, 256>>>(x, np, nc);
    k_m3    <<<256, 256>>>(bias, out, yf);
}

// round 14
// speedup vs baseline: 1.3754x; 1.3754x over previous
#include <cuda_runtime.h>
#include <cstdint>
#include <cstring>
#include <vector>
#include <thread>
#include <algorithm>

// ---------------------------------------------------------------------------
// quan_Linear_fi — R14: R12 structure (host threefry -> sparse flips; M1
// stores c 268MB coalesced, M2 reloads) with fixed-overhead fusions:
//   * k_wq eliminated — M1 quantizes its block's w[o] row into smem
//     (bit-identical formula; M2 never needed wq)
//   * bitmap scatter + max-reg zeroing fused into the two uploader kernels
//   * 7 graph nodes (was 9)
// Flip set & hot-path arithmetic unchanged -> rel_err exactly 8.490434e-4.
// Planes: p 9..15, c 7..15, y 0..15.
// ---------------------------------------------------------------------------

#define FLIP_T  43008u
#define P_KMIN 9
#define P_NP   7
#define C_KMIN 7
#define C_NP   9
#define Y_NP   16

// Arena layout (uint32 units).
#define BM_P   0u          // 4096 words: 131072 row bits (p tensor)
#define BM_C   4096u       // 4096 words (c tensor)
#define ENT_P  8192u       // up to 8192 packed entries (j<<4 | plane)
#define ENT_C  16384u      // up to 8192 packed entries
#define COLW   24576u      // 512 floats: colmax|w|
#define COLX   25088u      // 512 floats: colmax|x|
#define ARENA_W 25600u

__device__ uint32_t g_arena[ARENA_W];
__device__ float    g_C[67108864];     // c = cumsum(p_faulty), 268 MB scratch
__device__ float    g_Y[131072];       // y before final bitflip, [b,o,s]
__device__ unsigned g_maxw_bits, g_maxp_bits, g_maxc_bits, g_maxy_bits;

// ------------- uploaders (kernel-arg -> arena, fused scatter) --------------
#define CHUNK_W 8000
struct Chunk { uint32_t n; uint32_t data[CHUNK_W]; };   // 32004-byte arg

// p-entry upload: store entries, scatter row bits, zero the max registers.
__global__ void k_upload_p(Chunk c) {
    unsigned i = blockIdx.x * blockDim.x + threadIdx.x;
    if (i == 0) {
        g_maxw_bits = 0u; g_maxp_bits = 0u; g_maxc_bits = 0u; g_maxy_bits = 0u;
    }
    if (i < c.n) {
        uint32_t v = c.data[i];
        g_arena[ENT_P + i] = v;
        unsigned row = v >> 13;                        // (j<<4)>>13 = j>>9
        atomicOr(&g_arena[BM_P + (row >> 5)], 1u << (row & 31));
    }
}

__global__ void k_upload_c(Chunk c) {
    unsigned i = blockIdx.x * blockDim.x + threadIdx.x;
    if (i < c.n) {
        uint32_t v = c.data[i];
        g_arena[ENT_C + i] = v;
        unsigned row = v >> 13;
        atomicOr(&g_arena[BM_C + (row >> 5)], 1u << (row & 31));
    }
}

struct YF { int n; uint32_t j[120]; uint32_t msk[120]; };

// 16-bit fixed-point quantize (round-nearest-even) + XOR fault.
__device__ __forceinline__ float qflip(float t, float inv, float scale,
                                       uint32_t mask) {
    float r = rintf(t * inv);
    r = fminf(fmaxf(r, -32768.0f), 32767.0f);
    if (mask) {
        int q = (int)r;
        q = (int)(((uint32_t)(q + 32768) ^ mask)) - 32768;
        r = (float)q;
    }
    return r * scale;
}

// Load this row's sparse flip masks into m[16] (elem = ch*128 + lane*4 + u).
__device__ __forceinline__ void load_masks(unsigned* m, int row, int lane,
                                           uint32_t bm_off, uint32_t ent_off,
                                           int n_ent) {
    #pragma unroll
    for (int e = 0; e < 16; ++e) m[e] = 0u;
    unsigned word = g_arena[bm_off + (row >> 5)];
    if ((word >> (row & 31)) & 1u) {
        int lo = 0, hi = n_ent;
        while (lo < hi) {
            int mid = (lo + hi) >> 1;
            if ((int)(g_arena[ent_off + mid] >> 13) < row) lo = mid + 1; else hi = mid;
        }
        while (lo < n_ent) {
            unsigned v = g_arena[ent_off + lo];
            if ((int)(v >> 13) != row) break;
            int e = (v >> 4) & 511;
            unsigned mask = 1u << (v & 15u);
            if (((e >> 2) & 31) == lane) {
                int slot = (e >> 7) * 4 + (e & 3);
                #pragma unroll
                for (int t2 = 0; t2 < 16; ++t2) if (slot == t2) m[t2] |= mask;
            }
            ++lo;
        }
    }
}

// ---------------------------- front kernels --------------------------------
__global__ void k_colmax(const float* __restrict__ x, const float* __restrict__ w) {
    int i = blockIdx.x;                  // column 0..511
    int t = threadIdx.x;                 // 256 threads
    float cw = fmaxf(fabsf(w[t * 512 + i]), fabsf(w[(t + 256) * 512 + i]));
    float cx = fabsf(x[t * 512 + i]);
    __shared__ float sw[8], sx[8];
    #pragma unroll
    for (int d = 16; d; d >>= 1) {
        cw = fmaxf(cw, __shfl_xor_sync(0xffffffffu, cw, d));
        cx = fmaxf(cx, __shfl_xor_sync(0xffffffffu, cx, d));
    }
    if ((t & 31) == 0) { sw[t >> 5] = cw; sx[t >> 5] = cx; }
    __syncthreads();
    if (t == 0) {
        float mw = sw[0], mx = sx[0];
        #pragma unroll
        for (int u = 1; u < 8; ++u) { mw = fmaxf(mw, sw[u]); mx = fmaxf(mx, sx[u]); }
        ((float*)g_arena)[COLW + i] = mw;
        ((float*)g_arena)[COLX + i] = mx;
        atomicMax(&g_maxw_bits, __float_as_uint(mw));   // maxw = max of colmaxes
    }
}

// max_p = max_i( colmax|x|_i * colmax|wq|_i )  (exact: fp monotone).
__global__ void k_scalep() {
    int i = threadIdx.x;                 // 512 threads, 1 block
    float step = __uint_as_float(g_maxw_bits) / 127.0f;
    float cw = ((float*)g_arena)[COLW + i];
    float cx = ((float*)g_arena)[COLX + i];
    float qw = fminf(rintf(cw / step), 127.0f) * step;
    __shared__ float sm[512];
    sm[i] = cx * qw;
    __syncthreads();
    for (int d = 256; d; d >>= 1) {
        if (i < d) sm[i] = fmaxf(sm[i], sm[i + d]);
        __syncthreads();
    }
    if (i == 0) g_maxp_bits = __float_as_uint(sm[0]);
}

// ---------------- M1: p quant+flip, cumsum, store c, max|c| ----------------
// One warp per (b, o, s) row; all 8 warps of a block share the same o, so the
// block quantizes w[o]'s row into smem once (bit-identical to the old k_wq).
__global__ void __launch_bounds__(256)
k_m1(const float* __restrict__ x, const float* __restrict__ w, int n_ent) {
    __shared__ float swq[512];
    __shared__ unsigned smax;
    int o_blk = ((int)blockIdx.x & 8191) >> 4;          // shared o for the block
    {
        float step = __uint_as_float(g_maxw_bits) / 127.0f;
        int t = threadIdx.x;
        #pragma unroll
        for (int r = 0; r < 2; ++r) {
            int e = t + r * 256;
            float q = rintf(w[o_blk * 512 + e] / step);
            q = fminf(fmaxf(q, -128.0f), 127.0f);
            swq[e] = q * step;
        }
        if (t == 0) smax = 0u;
    }
    __syncthreads();

    int wid  = (blockIdx.x * 256 + threadIdx.x) >> 5;   // 0..131071
    int lane = threadIdx.x & 31;
    int b  = wid >> 16;
    int s  = wid & 127;
    unsigned jbase = (unsigned)wid * 512u;

    unsigned m[16];
    load_masks(m, wid, lane, BM_P, ENT_P, n_ent);

    float mp = __uint_as_float(g_maxp_bits);
    float sp = mp / 32767.0f; if (!(sp > 0.0f)) sp = 1.0f;
    float ip = 1.0f / sp;
    const float4* X4 = (const float4*)(x + b * 65536 + s * 512);
    const float4* W4 = (const float4*)swq;
    float4* C4 = (float4*)(g_C + jbase);

    float carry = 0.0f, mx = 0.0f;
    #pragma unroll
    for (int ch = 0; ch < 4; ++ch) {
        int vi = ch * 32 + lane;
        float4 xv = X4[vi];
        float4 wv = W4[vi];
        float f0 = qflip(xv.x * wv.x, ip, sp, m[ch * 4 + 0]);
        float f1 = qflip(xv.y * wv.y, ip, sp, m[ch * 4 + 1]);
        float f2 = qflip(xv.z * wv.z, ip, sp, m[ch * 4 + 2]);
        float f3 = qflip(xv.w * wv.w, ip, sp, m[ch * 4 + 3]);
        float s1 = f0 + f1, s2 = s1 + f2, t = s2 + f3;
        float T = t;                                    // inclusive scan of lane sums
        #pragma unroll
        for (int d = 1; d < 32; d <<= 1) {
            float v = __shfl_up_sync(0xffffffffu, T, d);
            if (lane >= d) T += v;
        }
        float base = carry + (T - t);                   // exclusive prefix
        float4 cv;
        cv.x = base + f0; cv.y = base + s1; cv.z = base + s2; cv.w = base + t;
        __stcs(&C4[vi], cv);
        mx = fmaxf(mx, fmaxf(fmaxf(fabsf(cv.x), fabsf(cv.y)),
                             fmaxf(fabsf(cv.z), fabsf(cv.w))));
        carry += __shfl_sync(0xffffffffu, T, 31);
    }
    #pragma unroll
    for (int d = 16; d; d >>= 1) mx = fmaxf(mx, __shfl_xor_sync(0xffffffffu, mx, d));

    if (lane == 0) atomicMax(&smax, __float_as_uint(mx));
    __syncthreads();
    if (threadIdx.x == 0) atomicMax(&g_maxc_bits, smax);
}

// ---------------- M2: c quant+flip, c_error + y_sum, max|y| ----------------
__global__ void __launch_bounds__(256)
k_m2(int n_ent) {
    int wid  = (blockIdx.x * 256 + threadIdx.x) >> 5;   // 0..131071
    int lane = threadIdx.x & 31;
    unsigned jbase = (unsigned)wid * 512u;

    unsigned m[16];
    load_masks(m, wid, lane, BM_C, ENT_C, n_ent);

    float mc = __uint_as_float(g_maxc_bits);
    float sc2 = mc / 32767.0f; if (!(sc2 > 0.0f)) sc2 = 1.0f;
    float ic = 1.0f / sc2;
    const float4* C4 = (const float4*)(g_C + jbase);

    float e = 0.0f, d_first = 0.0f, d_last = 0.0f, y_last = 0.0f;
    #pragma unroll
    for (int ch = 0; ch < 4; ++ch) {
        float4 cv = __ldcs(&C4[ch * 32 + lane]);
        float f0 = qflip(cv.x, ic, sc2, m[ch * 4 + 0]);
        float f1 = qflip(cv.y, ic, sc2, m[ch * 4 + 1]);
        float f2 = qflip(cv.z, ic, sc2, m[ch * 4 + 2]);
        float f3 = qflip(cv.w, ic, sc2, m[ch * 4 + 3]);
        e += ((f0 - cv.x) + (f1 - cv.y)) + ((f2 - cv.z) + (f3 - cv.w));
        if (ch == 0 && lane == 0)  d_first = f0 - cv.x;               // i = 0
        if (ch == 3 && lane == 31) { d_last = f3 - cv.w; y_last = f3; } // i = 511
    }
    #pragma unroll
    for (int d = 16; d; d >>= 1) e += __shfl_xor_sync(0xffffffffu, e, d);
    d_first = __shfl_sync(0xffffffffu, d_first, 0);
    d_last  = __shfl_sync(0xffffffffu, d_last, 31);
    y_last  = __shfl_sync(0xffffffffu, y_last, 31);

    __shared__ unsigned smax;
    if (threadIdx.x == 0) smax = 0u;
    __syncthreads();
    if (lane == 0) {
        float y = y_last + (e - d_first - d_last);
        g_Y[wid] = y;                                   // [b,o,s] flat == wid
        atomicMax(&smax, __float_as_uint(fabsf(y)));
    }
    __syncthreads();
    if (threadIdx.x == 0) atomicMax(&g_maxy_bits, smax);
}

// ---------------- M3: final y bitflip + transpose + bias -------------------
__global__ void k_m3(const float* __restrict__ bias, float* __restrict__ out,
                     YF yf) {
    int t = blockIdx.x * blockDim.x + threadIdx.x;   // 0..65535
    int o = t & 511, s = t >> 9;
    float my = __uint_as_float(g_maxy_bits);
    float sy = my / 32767.0f; if (!(sy > 0.0f)) sy = 1.0f;
    float iy = 1.0f / sy;
    unsigned j0 = (unsigned)(o * 128 + s);
    unsigned j1 = j0 + 65536u;
    unsigned m0 = 0u, m1 = 0u;
    for (int i = 0; i < yf.n; ++i) {
        if (yf.j[i] == j0) m0 |= yf.msk[i];
        if (yf.j[i] == j1) m1 |= yf.msk[i];
    }
    float y0 = g_Y[j0];
    float y1 = g_Y[j1];
    float b  = bias[o];
    out[(0 * 128 + s) * 512 + o] = qflip(y0, iy, sy, m0) + b;
    out[(1 * 128 + s) * 512 + o] = qflip(y1, iy, sy, m1) + b;
}

// ---------------------------- host side ------------------------------------
struct HSched { uint32_t A0, B0, A1, B1, A2, B2, A3, B3, A4, B4, A5, B5; };

static void h_threefry(uint32_t k0, uint32_t k1, uint32_t x0, uint32_t x1,
                       uint32_t& o0, uint32_t& o1) {
    uint32_t k2 = k0 ^ k1 ^ 0x1BD11BDAu;
    auto rot = [](uint32_t v, int r) { return (v << r) | (v >> (32 - r)); };
    auto rnd = [&](int r) { x0 += x1; x1 = rot(x1, r); x1 ^= x0; };
    x0 += k0; x1 += k1;
    rnd(13); rnd(15); rnd(26); rnd(6);   x0 += k1; x1 += k2 + 1u;
    rnd(17); rnd(29); rnd(16); rnd(24);  x0 += k2; x1 += k0 + 2u;
    rnd(13); rnd(15); rnd(26); rnd(6);   x0 += k0; x1 += k1 + 3u;
    rnd(17); rnd(29); rnd(16); rnd(24);  x0 += k1; x1 += k2 + 4u;
    rnd(13); rnd(15); rnd(26); rnd(6);   x0 += k2; x1 += k0 + 5u;
    o0 = x0; o1 = x1;
}

static void h_foldin(uint32_t k0, uint32_t k1, uint32_t d,
                     uint32_t& o0, uint32_t& o1) {
    h_threefry(k0, k1, 0u, d, o0, o1);
}

static HSched h_sched(uint32_t k0, uint32_t k1) {
    uint32_t k2 = k0 ^ k1 ^ 0x1BD11BDAu;
    HSched s;
    s.A0 = k0; s.B0 = k1;
    s.A1 = k1; s.B1 = k2 + 1u;
    s.A2 = k2; s.B2 = k0 + 2u;
    s.A3 = k0; s.B3 = k1 + 3u;
    s.A4 = k1; s.B4 = k2 + 4u;
    s.A5 = k2; s.B5 = k0 + 5u;
    return s;
}

static inline uint32_t tf_host(const HSched& s, uint32_t j) {
    uint32_t x0 = s.A0, x1 = j + s.B0;
    auto R = [&](int r) { x0 += x1; x1 = (x1 << r) | (x1 >> (32 - r)); x1 ^= x0; };
    R(13); R(15); R(26); R(6);   x0 += s.A1; x1 += s.B1;
    R(17); R(29); R(16); R(24);  x0 += s.A2; x1 += s.B2;
    R(13); R(15); R(26); R(6);   x0 += s.A3; x1 += s.B3;
    R(17); R(29); R(16); R(24);  x0 += s.A4; x1 += s.B4;
    R(13); R(15); R(26); R(6);   x0 += s.A5; x1 += s.B5;
    return x0 ^ x1;
}

// Collect packed flips (j<<4 | plane), sorted ascending (j-major).
static void collect_packed(const HSched* scheds, const int* planes, int nk,
                           uint32_t N, std::vector<uint32_t>& out) {
    unsigned T = std::thread::hardware_concurrency();
    if (T == 0) T = 8;
    if (T > 48) T = 48;
    uint32_t chunk = ((N / T + 511u) / 512u) * 512u;
    if (chunk == 0) chunk = N;
    std::vector<std::vector<uint32_t>> res(T);
    auto work = [&](unsigned t) {
        uint64_t lo = (uint64_t)t * chunk;
        if (lo >= N) return;
        uint64_t hi = lo + chunk; if (hi > N) hi = N;
        auto& v = res[t];
        for (int k = 0; k < nk; ++k) {
            HSched s = scheds[k];
            uint32_t pl = (uint32_t)planes[k];
            for (uint64_t j = lo; j < hi; ++j)
                if (tf_host(s, (uint32_t)j) < FLIP_T)
                    v.push_back(((uint32_t)j << 4) | pl);
        }
        std::sort(v.begin(), v.end());
    };
    std::vector<std::thread> th;
    unsigned started = 0;
    try {
        for (; started < T; ++started) th.emplace_back(work, started);
    } catch (...) {}
    for (auto& x : th) x.join();
    for (unsigned t = started; t < T; ++t) work(t);   // serial fallback
    for (unsigned t = 0; t < T; ++t)
        out.insert(out.end(), res[t].begin(), res[t].end());
}

extern "C" void kernel_launch(void* const* d_in, const int* in_sizes, int n_in,
                              void* d_out, int out_size) {
    const float* x    = (const float*)d_in[0];
    const float* w    = (const float*)d_in[1];
    const float* bias = (const float*)d_in[2];
    float* out        = (float*)d_out;

    // fikey = jax.random.key(42) -> (0,42); per-tensor, per-plane keys.
    uint32_t p0, p1, c0, c1, y0, y1, a, b;
    h_foldin(0u, 42u, 0u, p0, p1);
    h_foldin(0u, 42u, 1u, c0, c1);
    h_foldin(0u, 42u, 2u, y0, y1);

    HSched sp[P_NP]; int bp[P_NP];
    for (int k = 0; k < P_NP; ++k) {
        h_foldin(p0, p1, (uint32_t)(P_KMIN + k), a, b);
        sp[k] = h_sched(a, b); bp[k] = P_KMIN + k;
    }
    HSched sc[C_NP]; int bc[C_NP];
    for (int k = 0; k < C_NP; ++k) {
        h_foldin(c0, c1, (uint32_t)(C_KMIN + k), a, b);
        sc[k] = h_sched(a, b); bc[k] = C_KMIN + k;
    }
    HSched sy[Y_NP]; int by[Y_NP];
    for (int k = 0; k < Y_NP; ++k) {
        h_foldin(y0, y1, (uint32_t)k, a, b);
        sy[k] = h_sched(a, b); by[k] = k;
    }

    // Host RNG: all flip positions (input-independent, deterministic).
    std::vector<uint32_t> fp, fc, fy;
    collect_packed(sp, bp, P_NP, 67108864u, fp);
    collect_packed(sc, bc, C_NP, 67108864u, fc);
    collect_packed(sy, by, Y_NP, 131072u, fy);

    int np = (int)std::min<size_t>(fp.size(), 8000);
    int nc = (int)std::min<size_t>(fc.size(), 8000);

    YF yf; yf.n = 0;
    for (uint32_t v : fy) {
        uint32_t j = v >> 4, msk = 1u << (v & 15u);
        if (yf.n && yf.j[yf.n - 1] == j) yf.msk[yf.n - 1] |= msk;
        else if (yf.n < 120) { yf.j[yf.n] = j; yf.msk[yf.n] = msk; ++yf.n; }
    }

    // Uploads with fused bitmap scatter (up_p also zeroes the max registers;
    // always launched, even with n=0).
    Chunk ch;
    ch.n = (uint32_t)np;
    if (np) memcpy(ch.data, fp.data(), np * 4);
    k_upload_p<<<(np > 0 ? (np + 255) / 256 : 1), 256>>>(ch);
    if (nc) {
        ch.n = (uint32_t)nc;
        memcpy(ch.data, fc.data(), nc * 4);
        k_upload_c<<<(nc + 255) / 256, 256>>>(ch);
    }

    k_colmax<<<512, 256>>>(x, w);
    k_scalep<<<1, 512>>>();
    k_m1    <<<16384, 256>>>(x, w, np);   // 131072 warps: one per (b,o,s)
    k_m2    <<<16384, 256>>>(nc);
    k_m3    <<<256, 256>>>(bias, out, yf);
}

// round 15
// speedup vs baseline: 1.4950x; 1.0870x over previous
#include <cuda_runtime.h>
#include <cstdint>
#include <cstring>
#include <vector>
#include <thread>
#include <algorithm>

// ---------------------------------------------------------------------------
// quan_Linear_fi — R15: R12 structure (host threefry -> sparse flips; M1
// stores c 268MB, M2 reloads) with FP-op dieting in the hot passes:
//   * ws = wq * (1/scale_p) precomputed once (k_ws) -> M1 does rint(x*ws):
//     one FMUL/elem eliminated
//   * magic-constant round-to-even replaces FRND (conversion-class) with two
//     full-rate FADDs in M1 and M2
//   * M2 computes f-c as a single FFMA(r, sc, -c)
//   * k_scalep folded into k_ws (per-block redundant reduction);
//     up_c fused with k_colmax (block-range split). 6 graph nodes.
// Planes: p 9..15, c 7..15, y 0..15; flip set unchanged.
// ---------------------------------------------------------------------------

#define FLIP_T  43008u
#define P_KMIN 9
#define P_NP   7
#define C_KMIN 7
#define C_NP   9
#define Y_NP   16

// Arena layout (uint32 units).
#define BM_P   0u          // 4096 words: 131072 row bits (p tensor)
#define BM_C   4096u       // 4096 words (c tensor)
#define ENT_P  8192u       // up to 8192 packed entries (j<<4 | plane)
#define ENT_C  16384u      // up to 8192 packed entries
#define COLW   24576u      // 512 floats: colmax|w|
#define COLX   25088u      // 512 floats: colmax|x|
#define ARENA_W 25600u

__device__ uint32_t g_arena[ARENA_W];
__device__ float    g_ws[512 * 512];   // wq * (1/scale_p)
__device__ float    g_C[67108864];     // c = cumsum(p_faulty), 268 MB scratch
__device__ float    g_Y[131072];       // y before final bitflip, [b,o,s]
__device__ unsigned g_maxw_bits, g_maxp_bits, g_maxc_bits, g_maxy_bits;

// Exact round-to-nearest-even for |t| < 2^22 (replaces FRND with 2 FADDs).
__device__ __forceinline__ float rn_even(float t) {
    const float MAGIC = 12582912.0f;   // 1.5 * 2^23
    float r = __fadd_rn(t, MAGIC);
    return __fadd_rn(r, -MAGIC);
}

// ------------- uploaders (kernel-arg -> arena, fused scatter) --------------
#define CHUNK_W 8000
struct Chunk { uint32_t n; uint32_t data[CHUNK_W]; };   // 32004-byte arg

// p-entry upload: store entries, scatter row bits, zero the max registers.
__global__ void k_upload_p(Chunk c) {
    unsigned i = blockIdx.x * blockDim.x + threadIdx.x;
    if (i == 0) {
        g_maxw_bits = 0u; g_maxp_bits = 0u; g_maxc_bits = 0u; g_maxy_bits = 0u;
    }
    if (i < c.n) {
        uint32_t v = c.data[i];
        g_arena[ENT_P + i] = v;
        unsigned row = v >> 13;                        // (j<<4)>>13 = j>>9
        atomicOr(&g_arena[BM_P + (row >> 5)], 1u << (row & 31));
    }
}

// Fused: blocks 0..511 do colmax (w and x column maxima + maxw);
// blocks 512.. upload c-entries + scatter BM_C bits.
__global__ void k_upc_colmax(Chunk c, const float* __restrict__ x,
                             const float* __restrict__ w) {
    int t = threadIdx.x;
    if (blockIdx.x < 512) {
        int i = blockIdx.x;                  // column 0..511
        float cw = fmaxf(fabsf(w[t * 512 + i]), fabsf(w[(t + 256) * 512 + i]));
        float cx = fabsf(x[t * 512 + i]);
        __shared__ float sw[8], sx[8];
        #pragma unroll
        for (int d = 16; d; d >>= 1) {
            cw = fmaxf(cw, __shfl_xor_sync(0xffffffffu, cw, d));
            cx = fmaxf(cx, __shfl_xor_sync(0xffffffffu, cx, d));
        }
        if ((t & 31) == 0) { sw[t >> 5] = cw; sx[t >> 5] = cx; }
        __syncthreads();
        if (t == 0) {
            float mw = sw[0], mx = sx[0];
            #pragma unroll
            for (int u = 1; u < 8; ++u) { mw = fmaxf(mw, sw[u]); mx = fmaxf(mx, sx[u]); }
            ((float*)g_arena)[COLW + i] = mw;
            ((float*)g_arena)[COLX + i] = mx;
            atomicMax(&g_maxw_bits, __float_as_uint(mw));
        }
    } else {
        unsigned i = (blockIdx.x - 512) * blockDim.x + t;
        if (i < c.n) {
            uint32_t v = c.data[i];
            g_arena[ENT_C + i] = v;
            unsigned row = v >> 13;
            atomicOr(&g_arena[BM_C + (row >> 5)], 1u << (row & 31));
        }
    }
}

struct YF { int n; uint32_t j[120]; uint32_t msk[120]; };

// Load this row's sparse flip masks into m[16] (elem = ch*128 + lane*4 + u).
__device__ __forceinline__ void load_masks(unsigned* m, int row, int lane,
                                           uint32_t bm_off, uint32_t ent_off,
                                           int n_ent) {
    #pragma unroll
    for (int e = 0; e < 16; ++e) m[e] = 0u;
    unsigned word = g_arena[bm_off + (row >> 5)];
    if ((word >> (row & 31)) & 1u) {
        int lo = 0, hi = n_ent;
        while (lo < hi) {
            int mid = (lo + hi) >> 1;
            if ((int)(g_arena[ent_off + mid] >> 13) < row) lo = mid + 1; else hi = mid;
        }
        while (lo < n_ent) {
            unsigned v = g_arena[ent_off + lo];
            if ((int)(v >> 13) != row) break;
            int e = (v >> 4) & 511;
            unsigned mask = 1u << (v & 15u);
            if (((e >> 2) & 31) == lane) {
                int slot = (e >> 7) * 4 + (e & 3);
                #pragma unroll
                for (int t2 = 0; t2 < 16; ++t2) if (slot == t2) m[t2] |= mask;
            }
            ++lo;
        }
    }
}

// k_ws: per-block redundant scale_p reduction (deterministic, identical in
// every block), then write ws = wq * (1/scale_p). Block 0 publishes maxp.
__global__ void k_ws(const float* __restrict__ w) {
    int t = threadIdx.x;                 // 256 threads, 512 blocks
    float step = __uint_as_float(g_maxw_bits) / 127.0f;
    const float* colw = (const float*)&g_arena[COLW];
    const float* colx = (const float*)&g_arena[COLX];

    // candidate max over the 2 columns this thread owns
    float v = 0.0f;
    #pragma unroll
    for (int r = 0; r < 2; ++r) {
        int i = t + r * 256;
        float qw = fminf(rintf(colw[i] / step), 127.0f) * step;
        v = fmaxf(v, colx[i] * qw);
    }
    __shared__ float red[8];
    #pragma unroll
    for (int d = 16; d; d >>= 1) v = fmaxf(v, __shfl_xor_sync(0xffffffffu, v, d));
    if ((t & 31) == 0) red[t >> 5] = v;
    __syncthreads();
    __shared__ float s_sp, s_ip;
    if (t == 0) {
        float mp = red[0];
        #pragma unroll
        for (int u = 1; u < 8; ++u) mp = fmaxf(mp, red[u]);
        float sp = mp / 32767.0f;
        sp = (sp > 0.0f) ? sp : 1.0f;
        s_sp = sp; s_ip = 1.0f / sp;
        if (blockIdx.x == 0) g_maxp_bits = __float_as_uint(mp);
    }
    __syncthreads();
    float ip = s_ip;

    // write ws for this block's 512 w elements
    #pragma unroll
    for (int r = 0; r < 2; ++r) {
        int e = blockIdx.x * 512 + t + r * 256;
        float q = rintf(w[e] / step);
        q = fminf(fmaxf(q, -128.0f), 127.0f);
        g_ws[e] = (q * step) * ip;
    }
}

// ---------------- M1: p quant+flip, cumsum, store c, max|c| ----------------
// quantize: r = rn_even(x*ws); clamp; optional flip; f = r*sp.
__device__ __forceinline__ float qflip_p(float xv, float wsv, float sp,
                                         uint32_t mask) {
    float r = rn_even(__fmul_rn(xv, wsv));
    r = fminf(fmaxf(r, -32768.0f), 32767.0f);
    if (mask) {
        int q = (int)r;
        q = (int)(((uint32_t)(q + 32768) ^ mask)) - 32768;
        r = (float)q;
    }
    return r * sp;
}

__global__ void __launch_bounds__(256)
k_m1(const float* __restrict__ x, int n_ent) {
    int wid  = (blockIdx.x * 256 + threadIdx.x) >> 5;   // 0..131071
    int lane = threadIdx.x & 31;
    int b  = wid >> 16;
    int os = wid & 65535;
    int o = os >> 7, s = os & 127;
    unsigned jbase = (unsigned)wid * 512u;

    unsigned m[16];
    load_masks(m, wid, lane, BM_P, ENT_P, n_ent);

    float mp = __uint_as_float(g_maxp_bits);
    float sp = mp / 32767.0f; if (!(sp > 0.0f)) sp = 1.0f;
    const float4* X4 = (const float4*)(x + b * 65536 + s * 512);
    const float4* W4 = (const float4*)(g_ws + o * 512);
    float4* C4 = (float4*)(g_C + jbase);

    float carry = 0.0f, mx = 0.0f;
    #pragma unroll
    for (int ch = 0; ch < 4; ++ch) {
        int vi = ch * 32 + lane;
        float4 xv = X4[vi];
        float4 wv = W4[vi];
        float f0 = qflip_p(xv.x, wv.x, sp, m[ch * 4 + 0]);
        float f1 = qflip_p(xv.y, wv.y, sp, m[ch * 4 + 1]);
        float f2 = qflip_p(xv.z, wv.z, sp, m[ch * 4 + 2]);
        float f3 = qflip_p(xv.w, wv.w, sp, m[ch * 4 + 3]);
        float s1 = f0 + f1, s2 = s1 + f2, t = s2 + f3;
        float T = t;                                    // inclusive scan of lane sums
        #pragma unroll
        for (int d = 1; d < 32; d <<= 1) {
            float v = __shfl_up_sync(0xffffffffu, T, d);
            if (lane >= d) T += v;
        }
        float base = carry + (T - t);                   // exclusive prefix
        float4 cv;
        cv.x = base + f0; cv.y = base + s1; cv.z = base + s2; cv.w = base + t;
        __stcs(&C4[vi], cv);
        mx = fmaxf(mx, fmaxf(fmaxf(fabsf(cv.x), fabsf(cv.y)),
                             fmaxf(fabsf(cv.z), fabsf(cv.w))));
        carry += __shfl_sync(0xffffffffu, T, 31);
    }
    #pragma unroll
    for (int d = 16; d; d >>= 1) mx = fmaxf(mx, __shfl_xor_sync(0xffffffffu, mx, d));

    __shared__ unsigned smax;
    if (threadIdx.x == 0) smax = 0u;
    __syncthreads();
    if (lane == 0) atomicMax(&smax, __float_as_uint(mx));
    __syncthreads();
    if (threadIdx.x == 0) atomicMax(&g_maxc_bits, smax);
}

// ---------------- M2: c quant+flip, c_error + y_sum, max|y| ----------------
// Returns the clamped+flipped integer-valued quantized c (not dequantized).
__device__ __forceinline__ float qround(float v, uint32_t mask) {
    float r = rn_even(v);
    r = fminf(fmaxf(r, -32768.0f), 32767.0f);
    if (mask) {
        int q = (int)r;
        q = (int)(((uint32_t)(q + 32768) ^ mask)) - 32768;
        r = (float)q;
    }
    return r;
}

__global__ void __launch_bounds__(256)
k_m2(int n_ent) {
    int wid  = (blockIdx.x * 256 + threadIdx.x) >> 5;   // 0..131071
    int lane = threadIdx.x & 31;
    unsigned jbase = (unsigned)wid * 512u;

    unsigned m[16];
    load_masks(m, wid, lane, BM_C, ENT_C, n_ent);

    float mc = __uint_as_float(g_maxc_bits);
    float sc2 = mc / 32767.0f; if (!(sc2 > 0.0f)) sc2 = 1.0f;
    float ic = 1.0f / sc2;
    const float4* C4 = (const float4*)(g_C + jbase);

    float e = 0.0f, d_first = 0.0f, d_last = 0.0f, y_last = 0.0f;
    #pragma unroll
    for (int ch = 0; ch < 4; ++ch) {
        float4 cv = __ldcs(&C4[ch * 32 + lane]);
        float r0 = qround(__fmul_rn(cv.x, ic), m[ch * 4 + 0]);
        float r1 = qround(__fmul_rn(cv.y, ic), m[ch * 4 + 1]);
        float r2 = qround(__fmul_rn(cv.z, ic), m[ch * 4 + 2]);
        float r3 = qround(__fmul_rn(cv.w, ic), m[ch * 4 + 3]);
        float d0 = __fmaf_rn(r0, sc2, -cv.x);
        float d1 = __fmaf_rn(r1, sc2, -cv.y);
        float d2 = __fmaf_rn(r2, sc2, -cv.z);
        float d3 = __fmaf_rn(r3, sc2, -cv.w);
        e += (d0 + d1) + (d2 + d3);
        if (ch == 0 && lane == 0)  d_first = d0;                        // i = 0
        if (ch == 3 && lane == 31) { d_last = d3; y_last = r3 * sc2; }  // i = 511
    }
    #pragma unroll
    for (int d = 16; d; d >>= 1) e += __shfl_xor_sync(0xffffffffu, e, d);
    d_first = __shfl_sync(0xffffffffu, d_first, 0);
    d_last  = __shfl_sync(0xffffffffu, d_last, 31);
    y_last  = __shfl_sync(0xffffffffu, y_last, 31);

    __shared__ unsigned smax;
    if (threadIdx.x == 0) smax = 0u;
    __syncthreads();
    if (lane == 0) {
        float y = y_last + (e - d_first - d_last);
        g_Y[wid] = y;                                   // [b,o,s] flat == wid
        atomicMax(&smax, __float_as_uint(fabsf(y)));
    }
    __syncthreads();
    if (threadIdx.x == 0) atomicMax(&g_maxy_bits, smax);
}

// ---------------- M3: final y bitflip + transpose + bias -------------------
__global__ void k_m3(const float* __restrict__ bias, float* __restrict__ out,
                     YF yf) {
    int t = blockIdx.x * blockDim.x + threadIdx.x;   // 0..65535
    int o = t & 511, s = t >> 9;
    float my = __uint_as_float(g_maxy_bits);
    float sy = my / 32767.0f; if (!(sy > 0.0f)) sy = 1.0f;
    float iy = 1.0f / sy;
    unsigned j0 = (unsigned)(o * 128 + s);
    unsigned j1 = j0 + 65536u;
    unsigned m0 = 0u, m1 = 0u;
    for (int i = 0; i < yf.n; ++i) {
        if (yf.j[i] == j0) m0 |= yf.msk[i];
        if (yf.j[i] == j1) m1 |= yf.msk[i];
    }
    float y0 = g_Y[j0];
    float y1 = g_Y[j1];
    float b  = bias[o];
    out[(0 * 128 + s) * 512 + o] = qround(__fmul_rn(y0, iy), m0) * sy + b;
    out[(1 * 128 + s) * 512 + o] = qround(__fmul_rn(y1, iy), m1) * sy + b;
}

// ---------------------------- host side ------------------------------------
struct HSched { uint32_t A0, B0, A1, B1, A2, B2, A3, B3, A4, B4, A5, B5; };

static void h_threefry(uint32_t k0, uint32_t k1, uint32_t x0, uint32_t x1,
                       uint32_t& o0, uint32_t& o1) {
    uint32_t k2 = k0 ^ k1 ^ 0x1BD11BDAu;
    auto rot = [](uint32_t v, int r) { return (v << r) | (v >> (32 - r)); };
    auto rnd = [&](int r) { x0 += x1; x1 = rot(x1, r); x1 ^= x0; };
    x0 += k0; x1 += k1;
    rnd(13); rnd(15); rnd(26); rnd(6);   x0 += k1; x1 += k2 + 1u;
    rnd(17); rnd(29); rnd(16); rnd(24);  x0 += k2; x1 += k0 + 2u;
    rnd(13); rnd(15); rnd(26); rnd(6);   x0 += k0; x1 += k1 + 3u;
    rnd(17); rnd(29); rnd(16); rnd(24);  x0 += k1; x1 += k2 + 4u;
    rnd(13); rnd(15); rnd(26); rnd(6);   x0 += k2; x1 += k0 + 5u;
    o0 = x0; o1 = x1;
}

static void h_foldin(uint32_t k0, uint32_t k1, uint32_t d,
                     uint32_t& o0, uint32_t& o1) {
    h_threefry(k0, k1, 0u, d, o0, o1);
}

static HSched h_sched(uint32_t k0, uint32_t k1) {
    uint32_t k2 = k0 ^ k1 ^ 0x1BD11BDAu;
    HSched s;
    s.A0 = k0; s.B0 = k1;
    s.A1 = k1; s.B1 = k2 + 1u;
    s.A2 = k2; s.B2 = k0 + 2u;
    s.A3 = k0; s.B3 = k1 + 3u;
    s.A4 = k1; s.B4 = k2 + 4u;
    s.A5 = k2; s.B5 = k0 + 5u;
    return s;
}

static inline uint32_t tf_host(const HSched& s, uint32_t j) {
    uint32_t x0 = s.A0, x1 = j + s.B0;
    auto R = [&](int r) { x0 += x1; x1 = (x1 << r) | (x1 >> (32 - r)); x1 ^= x0; };
    R(13); R(15); R(26); R(6);   x0 += s.A1; x1 += s.B1;
    R(17); R(29); R(16); R(24);  x0 += s.A2; x1 += s.B2;
    R(13); R(15); R(26); R(6);   x0 += s.A3; x1 += s.B3;
    R(17); R(29); R(16); R(24);  x0 += s.A4; x1 += s.B4;
    R(13); R(15); R(26); R(6);   x0 += s.A5; x1 += s.B5;
    return x0 ^ x1;
}

// Collect packed flips (j<<4 | plane), sorted ascending (j-major).
static void collect_packed(const HSched* scheds, const int* planes, int nk,
                           uint32_t N, std::vector<uint32_t>& out) {
    unsigned T = std::thread::hardware_concurrency();
    if (T == 0) T = 8;
    if (T > 48) T = 48;
    uint32_t chunk = ((N / T + 511u) / 512u) * 512u;
    if (chunk == 0) chunk = N;
    std::vector<std::vector<uint32_t>> res(T);
    auto work = [&](unsigned t) {
        uint64_t lo = (uint64_t)t * chunk;
        if (lo >= N) return;
        uint64_t hi = lo + chunk; if (hi > N) hi = N;
        auto& v = res[t];
        for (int k = 0; k < nk; ++k) {
            HSched s = scheds[k];
            uint32_t pl = (uint32_t)planes[k];
            for (uint64_t j = lo; j < hi; ++j)
                if (tf_host(s, (uint32_t)j) < FLIP_T)
                    v.push_back(((uint32_t)j << 4) | pl);
        }
        std::sort(v.begin(), v.end());
    };
    std::vector<std::thread> th;
    unsigned started = 0;
    try {
        for (; started < T; ++started) th.emplace_back(work, started);
    } catch (...) {}
    for (auto& x : th) x.join();
    for (unsigned t = started; t < T; ++t) work(t);   // serial fallback
    for (unsigned t = 0; t < T; ++t)
        out.insert(out.end(), res[t].begin(), res[t].end());
}

extern "C" void kernel_launch(void* const* d_in, const int* in_sizes, int n_in,
                              void* d_out, int out_size) {
    const float* x    = (const float*)d_in[0];
    const float* w    = (const float*)d_in[1];
    const float* bias = (const float*)d_in[2];
    float* out        = (float*)d_out;

    // fikey = jax.random.key(42) -> (0,42); per-tensor, per-plane keys.
    uint32_t p0, p1, c0, c1, y0, y1, a, b;
    h_foldin(0u, 42u, 0u, p0, p1);
    h_foldin(0u, 42u, 1u, c0, c1);
    h_foldin(0u, 42u, 2u, y0, y1);

    HSched sp[P_NP]; int bp[P_NP];
    for (int k = 0; k < P_NP; ++k) {
        h_foldin(p0, p1, (uint32_t)(P_KMIN + k), a, b);
        sp[k] = h_sched(a, b); bp[k] = P_KMIN + k;
    }
    HSched sc[C_NP]; int bc[C_NP];
    for (int k = 0; k < C_NP; ++k) {
        h_foldin(c0, c1, (uint32_t)(C_KMIN + k), a, b);
        sc[k] = h_sched(a, b); bc[k] = C_KMIN + k;
    }
    HSched sy[Y_NP]; int by[Y_NP];
    for (int k = 0; k < Y_NP; ++k) {
        h_foldin(y0, y1, (uint32_t)k, a, b);
        sy[k] = h_sched(a, b); by[k] = k;
    }

    // Host RNG: all flip positions (input-independent, deterministic).
    std::vector<uint32_t> fp, fc, fy;
    collect_packed(sp, bp, P_NP, 67108864u, fp);
    collect_packed(sc, bc, C_NP, 67108864u, fc);
    collect_packed(sy, by, Y_NP, 131072u, fy);

    int np = (int)std::min<size_t>(fp.size(), 8000);
    int nc = (int)std::min<size_t>(fc.size(), 8000);

    YF yf; yf.n = 0;
    for (uint32_t v : fy) {
        uint32_t j = v >> 4, msk = 1u << (v & 15u);
        if (yf.n && yf.j[yf.n - 1] == j) yf.msk[yf.n - 1] |= msk;
        else if (yf.n < 120) { yf.j[yf.n] = j; yf.msk[yf.n] = msk; ++yf.n; }
    }

    // Node 1: p-entry upload (zeroes max registers; always launched).
    Chunk ch;
    ch.n = (uint32_t)np;
    if (np) memcpy(ch.data, fp.data(), np * 4);
    k_upload_p<<<(np > 0 ? (np + 255) / 256 : 1), 256>>>(ch);

    // Node 2: fused c-entry upload + colmax.
    ch.n = (uint32_t)nc;
    if (nc) memcpy(ch.data, fc.data(), nc * 4);
    int gup = 512 + (nc > 0 ? (nc + 255) / 256 : 0);
    k_upc_colmax<<<gup, 256>>>(ch, x, w);

    // Nodes 3-6.
    k_ws<<<512, 256>>>(w);
    k_m1<<<16384, 256>>>(x, np);       // 131072 warps: one per (b,o,s)
    k_m2<<<16384, 256>>>(nc);
    k_m3<<<256, 256>>>(bias, out, yf);
}

// round 16
// speedup vs baseline: 1.7161x; 1.1479x over previous
#include <cuda_runtime.h>
#include <cstdint>
#include <cstring>
#include <vector>
#include <thread>
#include <algorithm>

// ---------------------------------------------------------------------------
// quan_Linear_fi — R16: R15 + row-granular fast path. ncu showed k_m1 is
// ALU/issue-bound (alu 44%, DRAM 33%): the per-element clamps and mask tests
// dominate. Only ~3.6% of rows contain any flip, so branch ONCE per row:
//   fast path: no mask regs, no per-element ISETP, no clamps (provably
//              redundant: |x*ws| <= 32767*(1+2.4e-7) < 32767.5)
//   slow path: R15 code with clamps (rare; whole-warp, no divergence)
// Planes: p 9..15, c 7..15, y 0..15; flip set unchanged.
// ---------------------------------------------------------------------------

#define FLIP_T  43008u
#define P_KMIN 9
#define P_NP   7
#define C_KMIN 7
#define C_NP   9
#define Y_NP   16

// Arena layout (uint32 units).
#define BM_P   0u          // 4096 words: 131072 row bits (p tensor)
#define BM_C   4096u       // 4096 words (c tensor)
#define ENT_P  8192u       // up to 8192 packed entries (j<<4 | plane)
#define ENT_C  16384u      // up to 8192 packed entries
#define COLW   24576u      // 512 floats: colmax|w|
#define COLX   25088u      // 512 floats: colmax|x|
#define ARENA_W 25600u

__device__ uint32_t g_arena[ARENA_W];
__device__ float    g_ws[512 * 512];   // wq * (1/scale_p)
__device__ float    g_C[67108864];     // c = cumsum(p_faulty), 268 MB scratch
__device__ float    g_Y[131072];       // y before final bitflip, [b,o,s]
__device__ unsigned g_maxw_bits, g_maxp_bits, g_maxc_bits, g_maxy_bits;

// Exact round-to-nearest-even for |t| < 2^22 (2 full-rate FADDs).
__device__ __forceinline__ float rn_even(float t) {
    const float MAGIC = 12582912.0f;   // 1.5 * 2^23
    float r = __fadd_rn(t, MAGIC);
    return __fadd_rn(r, -MAGIC);
}

// ------------- uploaders (kernel-arg -> arena, fused scatter) --------------
#define CHUNK_W 8000
struct Chunk { uint32_t n; uint32_t data[CHUNK_W]; };   // 32004-byte arg

__global__ void k_upload_p(Chunk c) {
    unsigned i = blockIdx.x * blockDim.x + threadIdx.x;
    if (i == 0) {
        g_maxw_bits = 0u; g_maxp_bits = 0u; g_maxc_bits = 0u; g_maxy_bits = 0u;
    }
    if (i < c.n) {
        uint32_t v = c.data[i];
        g_arena[ENT_P + i] = v;
        unsigned row = v >> 13;                        // (j<<4)>>13 = j>>9
        atomicOr(&g_arena[BM_P + (row >> 5)], 1u << (row & 31));
    }
}

// Fused: blocks 0..511 do colmax; blocks 512.. upload c-entries + BM_C bits.
__global__ void k_upc_colmax(Chunk c, const float* __restrict__ x,
                             const float* __restrict__ w) {
    int t = threadIdx.x;
    if (blockIdx.x < 512) {
        int i = blockIdx.x;                  // column 0..511
        float cw = fmaxf(fabsf(w[t * 512 + i]), fabsf(w[(t + 256) * 512 + i]));
        float cx = fabsf(x[t * 512 + i]);
        __shared__ float sw[8], sx[8];
        #pragma unroll
        for (int d = 16; d; d >>= 1) {
            cw = fmaxf(cw, __shfl_xor_sync(0xffffffffu, cw, d));
            cx = fmaxf(cx, __shfl_xor_sync(0xffffffffu, cx, d));
        }
        if ((t & 31) == 0) { sw[t >> 5] = cw; sx[t >> 5] = cx; }
        __syncthreads();
        if (t == 0) {
            float mw = sw[0], mx = sx[0];
            #pragma unroll
            for (int u = 1; u < 8; ++u) { mw = fmaxf(mw, sw[u]); mx = fmaxf(mx, sx[u]); }
            ((float*)g_arena)[COLW + i] = mw;
            ((float*)g_arena)[COLX + i] = mx;
            atomicMax(&g_maxw_bits, __float_as_uint(mw));
        }
    } else {
        unsigned i = (blockIdx.x - 512) * blockDim.x + t;
        if (i < c.n) {
            uint32_t v = c.data[i];
            g_arena[ENT_C + i] = v;
            unsigned row = v >> 13;
            atomicOr(&g_arena[BM_C + (row >> 5)], 1u << (row & 31));
        }
    }
}

struct YF { int n; uint32_t j[120]; uint32_t msk[120]; };

// Load this row's sparse flip masks into m[16] (elem = ch*128 + lane*4 + u).
// Only called on flip rows (bitmap bit already known set).
__device__ __noinline__ void load_masks(unsigned* m, int row, int lane,
                                        uint32_t ent_off, int n_ent) {
    #pragma unroll
    for (int e = 0; e < 16; ++e) m[e] = 0u;
    int lo = 0, hi = n_ent;
    while (lo < hi) {
        int mid = (lo + hi) >> 1;
        if ((int)(g_arena[ent_off + mid] >> 13) < row) lo = mid + 1; else hi = mid;
    }
    while (lo < n_ent) {
        unsigned v = g_arena[ent_off + lo];
        if ((int)(v >> 13) != row) break;
        int e = (v >> 4) & 511;
        unsigned mask = 1u << (v & 15u);
        if (((e >> 2) & 31) == lane) {
            int slot = (e >> 7) * 4 + (e & 3);
            #pragma unroll
            for (int t2 = 0; t2 < 16; ++t2) if (slot == t2) m[t2] |= mask;
        }
        ++lo;
    }
}

// k_ws: per-block redundant scale_p reduction, then ws = wq * (1/scale_p).
__global__ void k_ws(const float* __restrict__ w) {
    int t = threadIdx.x;                 // 256 threads, 512 blocks
    float step = __uint_as_float(g_maxw_bits) / 127.0f;
    const float* colw = (const float*)&g_arena[COLW];
    const float* colx = (const float*)&g_arena[COLX];

    float v = 0.0f;
    #pragma unroll
    for (int r = 0; r < 2; ++r) {
        int i = t + r * 256;
        float qw = fminf(rintf(colw[i] / step), 127.0f) * step;
        v = fmaxf(v, colx[i] * qw);
    }
    __shared__ float red[8];
    #pragma unroll
    for (int d = 16; d; d >>= 1) v = fmaxf(v, __shfl_xor_sync(0xffffffffu, v, d));
    if ((t & 31) == 0) red[t >> 5] = v;
    __syncthreads();
    __shared__ float s_ip;
    if (t == 0) {
        float mp = red[0];
        #pragma unroll
        for (int u = 1; u < 8; ++u) mp = fmaxf(mp, red[u]);
        float sp = mp / 32767.0f;
        sp = (sp > 0.0f) ? sp : 1.0f;
        s_ip = 1.0f / sp;
        if (blockIdx.x == 0) g_maxp_bits = __float_as_uint(mp);
    }
    __syncthreads();
    float ip = s_ip;

    #pragma unroll
    for (int r = 0; r < 2; ++r) {
        int e = blockIdx.x * 512 + t + r * 256;
        float q = rintf(w[e] / step);
        q = fminf(fmaxf(q, -128.0f), 127.0f);
        g_ws[e] = (q * step) * ip;
    }
}

// Flip+clamp (slow path only).
__device__ __forceinline__ float flip_q(float r, uint32_t mask) {
    r = fminf(fmaxf(r, -32768.0f), 32767.0f);
    if (mask) {
        int q = (int)r;
        q = (int)(((uint32_t)(q + 32768) ^ mask)) - 32768;
        r = (float)q;
    }
    return r;
}

// ---------------- M1: p quant+flip, cumsum, store c, max|c| ----------------
__global__ void __launch_bounds__(256)
k_m1(const float* __restrict__ x, int n_ent) {
    int wid  = (blockIdx.x * 256 + threadIdx.x) >> 5;   // 0..131071
    int lane = threadIdx.x & 31;
    int b  = wid >> 16;
    int os = wid & 65535;
    int o = os >> 7, s = os & 127;
    unsigned jbase = (unsigned)wid * 512u;

    float mp = __uint_as_float(g_maxp_bits);
    float sp = mp / 32767.0f; if (!(sp > 0.0f)) sp = 1.0f;
    const float4* X4 = (const float4*)(x + b * 65536 + s * 512);
    const float4* W4 = (const float4*)(g_ws + o * 512);
    float4* C4 = (float4*)(g_C + jbase);

    bool has = (g_arena[BM_P + (wid >> 5)] >> (wid & 31)) & 1u;
    float carry = 0.0f, mx = 0.0f;

    if (!has) {
        // ---- fast path: no masks, no clamps ----
        #pragma unroll
        for (int ch = 0; ch < 4; ++ch) {
            int vi = ch * 32 + lane;
            float4 xv = X4[vi];
            float4 wv = W4[vi];
            float f0 = rn_even(__fmul_rn(xv.x, wv.x)) * sp;
            float f1 = rn_even(__fmul_rn(xv.y, wv.y)) * sp;
            float f2 = rn_even(__fmul_rn(xv.z, wv.z)) * sp;
            float f3 = rn_even(__fmul_rn(xv.w, wv.w)) * sp;
            float s1 = f0 + f1, s2 = s1 + f2, t = s2 + f3;
            float T = t;
            #pragma unroll
            for (int d = 1; d < 32; d <<= 1) {
                float v = __shfl_up_sync(0xffffffffu, T, d);
                if (lane >= d) T += v;
            }
            float base = carry + (T - t);
            float4 cv;
            cv.x = base + f0; cv.y = base + s1; cv.z = base + s2; cv.w = base + t;
            __stcs(&C4[vi], cv);
            mx = fmaxf(mx, fmaxf(fmaxf(fabsf(cv.x), fabsf(cv.y)),
                                 fmaxf(fabsf(cv.z), fabsf(cv.w))));
            carry += __shfl_sync(0xffffffffu, T, 31);
        }
    } else {
        // ---- slow path: rare rows with flips ----
        unsigned m[16];
        load_masks(m, wid, lane, ENT_P, n_ent);
        #pragma unroll
        for (int ch = 0; ch < 4; ++ch) {
            int vi = ch * 32 + lane;
            float4 xv = X4[vi];
            float4 wv = W4[vi];
            float f0 = flip_q(rn_even(__fmul_rn(xv.x, wv.x)), m[ch * 4 + 0]) * sp;
            float f1 = flip_q(rn_even(__fmul_rn(xv.y, wv.y)), m[ch * 4 + 1]) * sp;
            float f2 = flip_q(rn_even(__fmul_rn(xv.z, wv.z)), m[ch * 4 + 2]) * sp;
            float f3 = flip_q(rn_even(__fmul_rn(xv.w, wv.w)), m[ch * 4 + 3]) * sp;
            float s1 = f0 + f1, s2 = s1 + f2, t = s2 + f3;
            float T = t;
            #pragma unroll
            for (int d = 1; d < 32; d <<= 1) {
                float v = __shfl_up_sync(0xffffffffu, T, d);
                if (lane >= d) T += v;
            }
            float base = carry + (T - t);
            float4 cv;
            cv.x = base + f0; cv.y = base + s1; cv.z = base + s2; cv.w = base + t;
            __stcs(&C4[vi], cv);
            mx = fmaxf(mx, fmaxf(fmaxf(fabsf(cv.x), fabsf(cv.y)),
                                 fmaxf(fabsf(cv.z), fabsf(cv.w))));
            carry += __shfl_sync(0xffffffffu, T, 31);
        }
    }
    #pragma unroll
    for (int d = 16; d; d >>= 1) mx = fmaxf(mx, __shfl_xor_sync(0xffffffffu, mx, d));

    __shared__ unsigned smax;
    if (threadIdx.x == 0) smax = 0u;
    __syncthreads();
    if (lane == 0) atomicMax(&smax, __float_as_uint(mx));
    __syncthreads();
    if (threadIdx.x == 0) atomicMax(&g_maxc_bits, smax);
}

// ---------------- M2: c quant+flip, c_error + y_sum, max|y| ----------------
__global__ void __launch_bounds__(256)
k_m2(int n_ent) {
    int wid  = (blockIdx.x * 256 + threadIdx.x) >> 5;   // 0..131071
    int lane = threadIdx.x & 31;
    unsigned jbase = (unsigned)wid * 512u;

    float mc = __uint_as_float(g_maxc_bits);
    float sc2 = mc / 32767.0f; if (!(sc2 > 0.0f)) sc2 = 1.0f;
    float ic = 1.0f / sc2;
    const float4* C4 = (const float4*)(g_C + jbase);

    bool has = (g_arena[BM_C + (wid >> 5)] >> (wid & 31)) & 1u;
    float e = 0.0f, d_first = 0.0f, d_last = 0.0f, y_last = 0.0f;

    if (!has) {
        // ---- fast path: no masks, no clamps ----
        #pragma unroll
        for (int ch = 0; ch < 4; ++ch) {
            float4 cv = __ldcs(&C4[ch * 32 + lane]);
            float r0 = rn_even(__fmul_rn(cv.x, ic));
            float r1 = rn_even(__fmul_rn(cv.y, ic));
            float r2 = rn_even(__fmul_rn(cv.z, ic));
            float r3 = rn_even(__fmul_rn(cv.w, ic));
            float d0 = __fmaf_rn(r0, sc2, -cv.x);
            float d1 = __fmaf_rn(r1, sc2, -cv.y);
            float d2 = __fmaf_rn(r2, sc2, -cv.z);
            float d3 = __fmaf_rn(r3, sc2, -cv.w);
            e += (d0 + d1) + (d2 + d3);
            if (ch == 0 && lane == 0)  d_first = d0;
            if (ch == 3 && lane == 31) { d_last = d3; y_last = r3 * sc2; }
        }
    } else {
        unsigned m[16];
        load_masks(m, wid, lane, ENT_C, n_ent);
        #pragma unroll
        for (int ch = 0; ch < 4; ++ch) {
            float4 cv = __ldcs(&C4[ch * 32 + lane]);
            float r0 = flip_q(rn_even(__fmul_rn(cv.x, ic)), m[ch * 4 + 0]);
            float r1 = flip_q(rn_even(__fmul_rn(cv.y, ic)), m[ch * 4 + 1]);
            float r2 = flip_q(rn_even(__fmul_rn(cv.z, ic)), m[ch * 4 + 2]);
            float r3 = flip_q(rn_even(__fmul_rn(cv.w, ic)), m[ch * 4 + 3]);
            float d0 = __fmaf_rn(r0, sc2, -cv.x);
            float d1 = __fmaf_rn(r1, sc2, -cv.y);
            float d2 = __fmaf_rn(r2, sc2, -cv.z);
            float d3 = __fmaf_rn(r3, sc2, -cv.w);
            e += (d0 + d1) + (d2 + d3);
            if (ch == 0 && lane == 0)  d_first = d0;
            if (ch == 3 && lane == 31) { d_last = d3; y_last = r3 * sc2; }
        }
    }
    #pragma unroll
    for (int d = 16; d; d >>= 1) e += __shfl_xor_sync(0xffffffffu, e, d);
    d_first = __shfl_sync(0xffffffffu, d_first, 0);
    d_last  = __shfl_sync(0xffffffffu, d_last, 31);
    y_last  = __shfl_sync(0xffffffffu, y_last, 31);

    __shared__ unsigned smax;
    if (threadIdx.x == 0) smax = 0u;
    __syncthreads();
    if (lane == 0) {
        float y = y_last + (e - d_first - d_last);
        g_Y[wid] = y;                                   // [b,o,s] flat == wid
        atomicMax(&smax, __float_as_uint(fabsf(y)));
    }
    __syncthreads();
    if (threadIdx.x == 0) atomicMax(&g_maxy_bits, smax);
}

// ---------------- M3: final y bitflip + transpose + bias -------------------
__global__ void k_m3(const float* __restrict__ bias, float* __restrict__ out,
                     YF yf) {
    int t = blockIdx.x * blockDim.x + threadIdx.x;   // 0..65535
    int o = t & 511, s = t >> 9;
    float my = __uint_as_float(g_maxy_bits);
    float sy = my / 32767.0f; if (!(sy > 0.0f)) sy = 1.0f;
    float iy = 1.0f / sy;
    unsigned j0 = (unsigned)(o * 128 + s);
    unsigned j1 = j0 + 65536u;
    unsigned m0 = 0u, m1 = 0u;
    for (int i = 0; i < yf.n; ++i) {
        if (yf.j[i] == j0) m0 |= yf.msk[i];
        if (yf.j[i] == j1) m1 |= yf.msk[i];
    }
    float y0 = g_Y[j0];
    float y1 = g_Y[j1];
    float b  = bias[o];
    out[(0 * 128 + s) * 512 + o] = flip_q(rn_even(__fmul_rn(y0, iy)), m0) * sy + b;
    out[(1 * 128 + s) * 512 + o] = flip_q(rn_even(__fmul_rn(y1, iy)), m1) * sy + b;
}

// ---------------------------- host side ------------------------------------
struct HSched { uint32_t A0, B0, A1, B1, A2, B2, A3, B3, A4, B4, A5, B5; };

static void h_threefry(uint32_t k0, uint32_t k1, uint32_t x0, uint32_t x1,
                       uint32_t& o0, uint32_t& o1) {
    uint32_t k2 = k0 ^ k1 ^ 0x1BD11BDAu;
    auto rot = [](uint32_t v, int r) { return (v << r) | (v >> (32 - r)); };
    auto rnd = [&](int r) { x0 += x1; x1 = rot(x1, r); x1 ^= x0; };
    x0 += k0; x1 += k1;
    rnd(13); rnd(15); rnd(26); rnd(6);   x0 += k1; x1 += k2 + 1u;
    rnd(17); rnd(29); rnd(16); rnd(24);  x0 += k2; x1 += k0 + 2u;
    rnd(13); rnd(15); rnd(26); rnd(6);   x0 += k0; x1 += k1 + 3u;
    rnd(17); rnd(29); rnd(16); rnd(24);  x0 += k1; x1 += k2 + 4u;
    rnd(13); rnd(15); rnd(26); rnd(6);   x0 += k2; x1 += k0 + 5u;
    o0 = x0; o1 = x1;
}

static void h_foldin(uint32_t k0, uint32_t k1, uint32_t d,
                     uint32_t& o0, uint32_t& o1) {
    h_threefry(k0, k1, 0u, d, o0, o1);
}

static HSched h_sched(uint32_t k0, uint32_t k1) {
    uint32_t k2 = k0 ^ k1 ^ 0x1BD11BDAu;
    HSched s;
    s.A0 = k0; s.B0 = k1;
    s.A1 = k1; s.B1 = k2 + 1u;
    s.A2 = k2; s.B2 = k0 + 2u;
    s.A3 = k0; s.B3 = k1 + 3u;
    s.A4 = k1; s.B4 = k2 + 4u;
    s.A5 = k2; s.B5 = k0 + 5u;
    return s;
}

static inline uint32_t tf_host(const HSched& s, uint32_t j) {
    uint32_t x0 = s.A0, x1 = j + s.B0;
    auto R = [&](int r) { x0 += x1; x1 = (x1 << r) | (x1 >> (32 - r)); x1 ^= x0; };
    R(13); R(15); R(26); R(6);   x0 += s.A1; x1 += s.B1;
    R(17); R(29); R(16); R(24);  x0 += s.A2; x1 += s.B2;
    R(13); R(15); R(26); R(6);   x0 += s.A3; x1 += s.B3;
    R(17); R(29); R(16); R(24);  x0 += s.A4; x1 += s.B4;
    R(13); R(15); R(26); R(6);   x0 += s.A5; x1 += s.B5;
    return x0 ^ x1;
}

// Collect packed flips (j<<4 | plane), sorted ascending (j-major).
static void collect_packed(const HSched* scheds, const int* planes, int nk,
                           uint32_t N, std::vector<uint32_t>& out) {
    unsigned T = std::thread::hardware_concurrency();
    if (T == 0) T = 8;
    if (T > 48) T = 48;
    uint32_t chunk = ((N / T + 511u) / 512u) * 512u;
    if (chunk == 0) chunk = N;
    std::vector<std::vector<uint32_t>> res(T);
    auto work = [&](unsigned t) {
        uint64_t lo = (uint64_t)t * chunk;
        if (lo >= N) return;
        uint64_t hi = lo + chunk; if (hi > N) hi = N;
        auto& v = res[t];
        for (int k = 0; k < nk; ++k) {
            HSched s = scheds[k];
            uint32_t pl = (uint32_t)planes[k];
            for (uint64_t j = lo; j < hi; ++j)
                if (tf_host(s, (uint32_t)j) < FLIP_T)
                    v.push_back(((uint32_t)j << 4) | pl);
        }
        std::sort(v.begin(), v.end());
    };
    std::vector<std::thread> th;
    unsigned started = 0;
    try {
        for (; started < T; ++started) th.emplace_back(work, started);
    } catch (...) {}
    for (auto& x : th) x.join();
    for (unsigned t = started; t < T; ++t) work(t);   // serial fallback
    for (unsigned t = 0; t < T; ++t)
        out.insert(out.end(), res[t].begin(), res[t].end());
}

extern "C" void kernel_launch(void* const* d_in, const int* in_sizes, int n_in,
                              void* d_out, int out_size) {
    const float* x    = (const float*)d_in[0];
    const float* w    = (const float*)d_in[1];
    const float* bias = (const float*)d_in[2];
    float* out        = (float*)d_out;

    // fikey = jax.random.key(42) -> (0,42); per-tensor, per-plane keys.
    uint32_t p0, p1, c0, c1, y0, y1, a, b;
    h_foldin(0u, 42u, 0u, p0, p1);
    h_foldin(0u, 42u, 1u, c0, c1);
    h_foldin(0u, 42u, 2u, y0, y1);

    HSched sp[P_NP]; int bp[P_NP];
    for (int k = 0; k < P_NP; ++k) {
        h_foldin(p0, p1, (uint32_t)(P_KMIN + k), a, b);
        sp[k] = h_sched(a, b); bp[k] = P_KMIN + k;
    }
    HSched sc[C_NP]; int bc[C_NP];
    for (int k = 0; k < C_NP; ++k) {
        h_foldin(c0, c1, (uint32_t)(C_KMIN + k), a, b);
        sc[k] = h_sched(a, b); bc[k] = C_KMIN + k;
    }
    HSched sy[Y_NP]; int by[Y_NP];
    for (int k = 0; k < Y_NP; ++k) {
        h_foldin(y0, y1, (uint32_t)k, a, b);
        sy[k] = h_sched(a, b); by[k] = k;
    }

    // Host RNG: all flip positions (input-independent, deterministic).
    std::vector<uint32_t> fp, fc, fy;
    collect_packed(sp, bp, P_NP, 67108864u, fp);
    collect_packed(sc, bc, C_NP, 67108864u, fc);
    collect_packed(sy, by, Y_NP, 131072u, fy);

    int np = (int)std::min<size_t>(fp.size(), 8000);
    int nc = (int)std::min<size_t>(fc.size(), 8000);

    YF yf; yf.n = 0;
    for (uint32_t v : fy) {
        uint32_t j = v >> 4, msk = 1u << (v & 15u);
        if (yf.n && yf.j[yf.n - 1] == j) yf.msk[yf.n - 1] |= msk;
        else if (yf.n < 120) { yf.j[yf.n] = j; yf.msk[yf.n] = msk; ++yf.n; }
    }

    // Node 1: p-entry upload (zeroes max registers; always launched).
    Chunk ch;
    ch.n = (uint32_t)np;
    if (np) memcpy(ch.data, fp.data(), np * 4);
    k_upload_p<<<(np > 0 ? (np + 255) / 256 : 1), 256>>>(ch);

    // Node 2: fused c-entry upload + colmax.
    ch.n = (uint32_t)nc;
    if (nc) memcpy(ch.data, fc.data(), nc * 4);
    int gup = 512 + (nc > 0 ? (nc + 255) / 256 : 0);
    k_upc_colmax<<<gup, 256>>>(ch, x, w);

    // Nodes 3-6.
    k_ws<<<512, 256>>>(w);
    k_m1<<<16384, 256>>>(x, np);       // 131072 warps: one per (b,o,s)
    k_m2<<<16384, 256>>>(nc);
    k_m3<<<256, 256>>>(bias, out, yf);
}